// round 15
// baseline (speedup 1.0000x reference)
#include <cuda_runtime.h>
#include <cuda_bf16.h>
#include <stdint.h>

// LUT_82085414961764: out = a[idx]*d + b[idx], idx = searchsorted(x, d, 'left')
// R14: fused table NB=4096 with THREE entry kinds (empty / 1-bkpt / multi):
//   empty  : e = (a[lo], b[lo])                      -> 1 LDS.64, FMA, done
//   1-bkpt : e.x = 0x7F800000|lo, e.y = x_m          -> idx = lo + (x_m < d); gather
//   multi  : e.x = 0xFF800000|lo (sign bit set)      -> sentinel scan from lo; gather
// Exponent-255 tag can't collide (a,b finite); sign bit distinguishes kinds.
// Bin function t = fmaf(v, scale, shift): monotone (scale>=0), IDENTICAL at
// build & query, so lo is a provably correct lower bound. 44 KB smem -> 4 CTAs/SM.

#define KMAX 1024
#define NB   4096

__global__ __launch_bounds__(512, 4)
void lut_kernel(const float* __restrict__ data,
                const float* __restrict__ x,
                const float* __restrict__ a,
                const float* __restrict__ b,
                float* __restrict__ out,
                int K, unsigned n)
{
    __shared__ float2 fused[NB];
    __shared__ float  x_s[KMAX + 1];
    __shared__ float2 ab_s[KMAX + 1];

    const int tid = threadIdx.x;
    const int bd  = blockDim.x;

    // ---- build phase ----------------------------------------------------
    for (int i = tid; i < K; i += bd)  x_s[i] = x[i];
    for (int i = tid; i <= K; i += bd) ab_s[i] = make_float2(a[i], b[i]);
    if (tid == 0) x_s[K] = __int_as_float(0x7F800000);  // +inf sentinel
    __syncthreads();

    const float LO    = x_s[0];
    const float span  = x_s[K - 1] - LO;
    const float scale = (span > 0.0f) ? ((float)NB / span) : 0.0f;
    const float shift = -LO * scale;
    const float NBf   = (float)NB;

    // monotone bin function — identical expression at build and query
    auto g = [&](float v) -> int {
        float t = fmaf(v, scale, shift);
        if (t < 0.0f) return 0;
        if (t >= NBf) return NB - 1;
        return (int)t;
    };

    for (int bin = tid; bin < NB; bin += bd) {
        int lo = 0, hi = K;
        while (lo < hi) {
            int mid = (lo + hi) >> 1;
            if (g(x_s[mid]) < bin) lo = mid + 1; else hi = mid;
        }
        float2 e;
        bool flagged = (lo < K) && (g(x_s[lo]) == bin);
        if (!flagged) {
            e = ab_s[lo];                         // empty: direct coefficients
        } else if (!((lo + 1 < K) && (g(x_s[lo + 1]) == bin))) {
            e.x = __uint_as_float(0x7F800000u | (unsigned)lo);  // single bkpt
            e.y = x_s[lo];                        // the breakpoint value
        } else {
            e.x = __uint_as_float(0xFF800000u | (unsigned)lo);  // multi: scan
            e.y = 0.0f;
        }
        fused[bin] = e;
    }
    __syncthreads();

    // single-element path (tail)
    auto lut1 = [&](float d) -> float {
        float t = fmaf(d, scale, shift);
        int bin;
        if (t < 0.0f)      bin = 0;
        else if (t >= NBf) bin = NB - 1;
        else               bin = (int)t;
        float2 e = fused[bin];
        unsigned ux = __float_as_uint(e.x);
        if ((ux & 0x7F800000u) == 0x7F800000u) {
            int idx = (int)(ux & 0x7FFFu);
            if ((int)ux < 0) {                    // multi-breakpoint: scan
                while (x_s[idx] < d) ++idx;       // sentinel-terminated
            } else {                              // single breakpoint
                idx += (e.y < d);
            }
            e = ab_s[idx];
        }
        return fmaf(e.x, d, e.y);
    };

    const unsigned n4 = n >> 2;
    const float4* __restrict__ in4  = (const float4*)data;
    float4* __restrict__       out4 = (float4*)out;
    const unsigned stride = (unsigned)gridDim.x * (unsigned)bd;

    // ---- main loop: one float4 per thread per iter, stage-structured ----
    for (unsigned i = (unsigned)blockIdx.x * (unsigned)bd + (unsigned)tid;
         i < n4; i += stride) {
        float4 v = in4[i];
        float dv[4] = {v.x, v.y, v.z, v.w};
        float2 ev[4];

        // stage 1: bins + fused loads (4 independent LDS.64)
        #pragma unroll
        for (int j = 0; j < 4; ++j) {
            float t = fmaf(dv[j], scale, shift);
            int bin;
            if (t < 0.0f)      bin = 0;
            else if (t >= NBf) bin = NB - 1;
            else               bin = (int)t;
            ev[j] = fused[bin];
        }

        // stage 2: tagged lanes resolve index and gather coefficients
        #pragma unroll
        for (int j = 0; j < 4; ++j) {
            unsigned ux = __float_as_uint(ev[j].x);
            if ((ux & 0x7F800000u) == 0x7F800000u) {
                int idx = (int)(ux & 0x7FFFu);
                if ((int)ux < 0) {                 // multi: sentinel scan
                    while (x_s[idx] < dv[j]) ++idx;
                } else {                           // single: one compare
                    idx += (ev[j].y < dv[j]);
                }
                ev[j] = ab_s[idx];
            }
        }

        // stage 3: FMA + store
        float4 r;
        r.x = fmaf(ev[0].x, dv[0], ev[0].y);
        r.y = fmaf(ev[1].x, dv[1], ev[1].y);
        r.z = fmaf(ev[2].x, dv[2], ev[2].y);
        r.w = fmaf(ev[3].x, dv[3], ev[3].y);
        out4[i] = r;
    }

    // scalar tail (n not divisible by 4)
    for (unsigned k = (n4 << 2) + (unsigned)blockIdx.x * (unsigned)bd + (unsigned)tid;
         k < n; k += stride) {
        out[k] = lut1(data[k]);
    }
}

extern "C" void kernel_launch(void* const* d_in, const int* in_sizes, int n_in,
                              void* d_out, int out_size)
{
    const float* data = (const float*)d_in[0];
    const float* x    = (const float*)d_in[1];
    const float* a    = (const float*)d_in[2];
    const float* b    = (const float*)d_in[3];
    float* out        = (float*)d_out;

    int K = in_sizes[1];
    if (K > KMAX) K = KMAX;  // problem constant is 1024
    unsigned n = (unsigned)out_size;

    const int threads = 512;
    int blocks = 608;  // 4 CTAs per SM on 152 SMs
    long long need = ((long long)n / 4 + threads - 1) / threads;
    if ((long long)blocks > need && need > 0) blocks = (int)need;
    if (blocks < 1) blocks = 1;

    lut_kernel<<<blocks, threads>>>(data, x, a, b, out, K, n);
}

// round 16
// speedup vs baseline: 1.0912x; 1.0912x over previous
#include <cuda_runtime.h>
#include <cuda_bf16.h>
#include <stdint.h>

// LUT_82085414961764: out = a[idx]*d + b[idx], idx = searchsorted(x, d, 'left')
// R15 = R13 champion (fused NB=4096, 4 CTAs/SM, batch-4) + ONE change:
// tagged entries carry e.y = x_s[lo] so the first scan compare is a register
// compare (no LDS). ~half of tagged lanes skip the scan loop entirely; the
// rest start one position later. Branch structure identical to R13.
//   empty  : e = (a[lo], b[lo])              -> 1 LDS.64, FMA, done
//   tagged : e.x = 0x7F800000|lo, e.y = x_s[lo]
//            idx = lo; if (e.y < d) { ++idx; while (x_s[idx] < d) ++idx; }
//            then gather ab_s[idx].
// Bin function t = fmaf(v, scale, shift): monotone (scale>=0), IDENTICAL at
// build & query, so lo is a provably correct lower bound. Tag (exp==255)
// cannot collide with finite a. 44 KB smem -> 4 CTAs/SM.

#define KMAX 1024
#define NB   4096

__global__ __launch_bounds__(512, 4)
void lut_kernel(const float* __restrict__ data,
                const float* __restrict__ x,
                const float* __restrict__ a,
                const float* __restrict__ b,
                float* __restrict__ out,
                int K, unsigned n)
{
    __shared__ float2 fused[NB];
    __shared__ float  x_s[KMAX + 1];
    __shared__ float2 ab_s[KMAX + 1];

    const int tid = threadIdx.x;
    const int bd  = blockDim.x;

    // ---- build phase ----------------------------------------------------
    for (int i = tid; i < K; i += bd)  x_s[i] = x[i];
    for (int i = tid; i <= K; i += bd) ab_s[i] = make_float2(a[i], b[i]);
    if (tid == 0) x_s[K] = __int_as_float(0x7F800000);  // +inf sentinel
    __syncthreads();

    const float LO    = x_s[0];
    const float span  = x_s[K - 1] - LO;
    const float scale = (span > 0.0f) ? ((float)NB / span) : 0.0f;
    const float shift = -LO * scale;
    const float NBf   = (float)NB;

    // monotone bin function — identical expression at build and query
    auto g = [&](float v) -> int {
        float t = fmaf(v, scale, shift);
        if (t < 0.0f) return 0;
        if (t >= NBf) return NB - 1;
        return (int)t;
    };

    for (int bin = tid; bin < NB; bin += bd) {
        int lo = 0, hi = K;
        while (lo < hi) {
            int mid = (lo + hi) >> 1;
            if (g(x_s[mid]) < bin) lo = mid + 1; else hi = mid;
        }
        float2 e;
        if (lo < K && g(x_s[lo]) == bin) {
            e.x = __uint_as_float(0x7F800000u | (unsigned)lo);  // tagged
            e.y = x_s[lo];                  // first breakpoint of this bin
        } else {
            e = ab_s[lo];                   // empty: direct coefficients
        }
        fused[bin] = e;
    }
    __syncthreads();

    // single-element path (tail)
    auto lut1 = [&](float d) -> float {
        float t = fmaf(d, scale, shift);
        int bin;
        if (t < 0.0f)      bin = 0;
        else if (t >= NBf) bin = NB - 1;
        else               bin = (int)t;
        float2 e = fused[bin];
        unsigned ux = __float_as_uint(e.x);
        if ((ux & 0x7F800000u) == 0x7F800000u) {
            int idx = (int)(ux & 0x7FFu);
            if (e.y < d) {                     // register compare (free)
                ++idx;
                while (x_s[idx] < d) ++idx;    // sentinel-terminated
            }
            e = ab_s[idx];
        }
        return fmaf(e.x, d, e.y);
    };

    const unsigned n4 = n >> 2;
    const float4* __restrict__ in4  = (const float4*)data;
    float4* __restrict__       out4 = (float4*)out;
    const unsigned stride = (unsigned)gridDim.x * (unsigned)bd;

    // ---- main loop: one float4 per thread per iter, stage-structured ----
    for (unsigned i = (unsigned)blockIdx.x * (unsigned)bd + (unsigned)tid;
         i < n4; i += stride) {
        float4 v = in4[i];
        float dv[4] = {v.x, v.y, v.z, v.w};
        float2 ev[4];

        // stage 1: bins + fused loads (4 independent LDS.64)
        #pragma unroll
        for (int j = 0; j < 4; ++j) {
            float t = fmaf(dv[j], scale, shift);
            int bin;
            if (t < 0.0f)      bin = 0;
            else if (t >= NBf) bin = NB - 1;
            else               bin = (int)t;
            ev[j] = fused[bin];
        }

        // stage 2: tagged lanes resolve index (first compare from register)
        #pragma unroll
        for (int j = 0; j < 4; ++j) {
            unsigned ux = __float_as_uint(ev[j].x);
            if ((ux & 0x7F800000u) == 0x7F800000u) {
                int idx = (int)(ux & 0x7FFu);
                if (ev[j].y < dv[j]) {             // free first compare
                    ++idx;
                    while (x_s[idx] < dv[j]) ++idx;
                }
                ev[j] = ab_s[idx];
            }
        }

        // stage 3: FMA + store
        float4 r;
        r.x = fmaf(ev[0].x, dv[0], ev[0].y);
        r.y = fmaf(ev[1].x, dv[1], ev[1].y);
        r.z = fmaf(ev[2].x, dv[2], ev[2].y);
        r.w = fmaf(ev[3].x, dv[3], ev[3].y);
        out4[i] = r;
    }

    // scalar tail (n not divisible by 4)
    for (unsigned k = (n4 << 2) + (unsigned)blockIdx.x * (unsigned)bd + (unsigned)tid;
         k < n; k += stride) {
        out[k] = lut1(data[k]);
    }
}

extern "C" void kernel_launch(void* const* d_in, const int* in_sizes, int n_in,
                              void* d_out, int out_size)
{
    const float* data = (const float*)d_in[0];
    const float* x    = (const float*)d_in[1];
    const float* a    = (const float*)d_in[2];
    const float* b    = (const float*)d_in[3];
    float* out        = (float*)d_out;

    int K = in_sizes[1];
    if (K > KMAX) K = KMAX;  // problem constant is 1024
    unsigned n = (unsigned)out_size;

    const int threads = 512;
    int blocks = 608;  // 4 CTAs per SM on 152 SMs
    long long need = ((long long)n / 4 + threads - 1) / threads;
    if ((long long)blocks > need && need > 0) blocks = (int)need;
    if (blocks < 1) blocks = 1;

    lut_kernel<<<blocks, threads>>>(data, x, a, b, out, K, n);
}